// round 12
// baseline (speedup 1.0000x reference)
#include <cuda_runtime.h>
#include <cuda_fp16.h>
#include <cstdint>

// Problem constants (ParacrineCascade: B=32, N=2048, D=128, K=3)
#define B_     32
#define N_     2048
#define D_     128
#define QT     64                 // queries per CTA  (2 CTAs/SM)
#define CT     64                 // candidates per tile (double-buffered)
#define NTILE  (N_ / CT)          // 32
#define NT     256                // threads (8 warps: 2m x 4n, warp tile 32x16)

// smem byte offsets
#define OFF_A    0                // 32KB  query tile (64 rows x 512B)
#define OFF_B    32768            // 2 x 32KB candidate tiles
#define OFF_MRGV 98304            // 64*4*3 f32 = 3072
#define OFF_MRGI 101376           // 64*4*3 int = 3072
#define OFF_SIDX 104448           // 64*3 int = 768
#define SMEM_TOTAL 105472         // ~103KB -> 2 CTAs/SM

// device scratch (no cudaMalloc allowed)
__device__ float              g_sq [B_ * N_];
__device__ unsigned long long g_ext[(size_t)B_ * N_ * 64];  // [row][64] u64: hi(32)|lo(32)

typedef unsigned long long u64;

__device__ __forceinline__ uint32_t smem_u32(const void* p) {
    uint32_t a;
    asm("{ .reg .u64 t; cvta.to.shared.u64 t, %1; cvt.u32.u64 %0, t; }"
        : "=r"(a) : "l"(p));
    return a;
}
__device__ __forceinline__ void cpasync16(uint32_t dst, const void* src) {
    asm volatile("cp.async.cg.shared.global [%0], [%1], 16;" :: "r"(dst), "l"(src));
}
#define CP_COMMIT() asm volatile("cp.async.commit_group;" ::: "memory")
#define CP_WAIT0()  asm volatile("cp.async.wait_group 0;" ::: "memory")

__device__ __forceinline__ void ldsm4(uint32_t& r0, uint32_t& r1,
                                      uint32_t& r2, uint32_t& r3, uint32_t addr) {
    asm volatile("ldmatrix.sync.aligned.m8n8.x4.shared.b16 {%0,%1,%2,%3}, [%4];"
                 : "=r"(r0), "=r"(r1), "=r"(r2), "=r"(r3) : "r"(addr));
}
__device__ __forceinline__ void mma16816(float& d0, float& d1, float& d2, float& d3,
                                         uint32_t a0, uint32_t a1, uint32_t a2, uint32_t a3,
                                         uint32_t b0, uint32_t b1) {
    asm volatile("mma.sync.aligned.m16n8k16.row.col.f32.f16.f16.f32 "
                 "{%0,%1,%2,%3}, {%4,%5,%6,%7}, {%8,%9}, {%0,%1,%2,%3};"
                 : "+f"(d0), "+f"(d1), "+f"(d2), "+f"(d3)
                 : "r"(a0), "r"(a1), "r"(a2), "r"(a3), "r"(b0), "r"(b1));
}

__device__ __forceinline__ void ins3(float s, int m, float* t, int* ix) {
    if (s < t[2]) {
        if (s < t[1]) {
            t[2] = t[1]; ix[2] = ix[1];
            if (s < t[0]) { t[1] = t[0]; ix[1] = ix[0]; t[0] = s; ix[0] = m; }
            else          { t[1] = s; ix[1] = m; }
        } else { t[2] = s; ix[2] = m; }
    }
}

// ---------------------------------------------------------------------------
// prep: squared norms (fp32) + fp16 hi/lo split -> g_ext. one warp per point.
// ---------------------------------------------------------------------------
__global__ void prep_kernel(const float* __restrict__ X) {
    int row  = (blockIdx.x * blockDim.x + threadIdx.x) >> 5;
    int lane = threadIdx.x & 31;
    if (row >= B_ * N_) return;
    float4 v = reinterpret_cast<const float4*>(X)[(size_t)row * 32 + lane];
    float s = v.x * v.x + v.y * v.y + v.z * v.z + v.w * v.w;
    #pragma unroll
    for (int off = 16; off; off >>= 1) s += __shfl_xor_sync(0xffffffffu, s, off);
    if (lane == 0) g_sq[row] = s;

    __half h0 = __float2half_rn(v.x), h1 = __float2half_rn(v.y);
    __half h2 = __float2half_rn(v.z), h3 = __float2half_rn(v.w);
    __half l0 = __float2half_rn(v.x - __half2float(h0));
    __half l1 = __float2half_rn(v.y - __half2float(h1));
    __half l2 = __float2half_rn(v.z - __half2float(h2));
    __half l3 = __float2half_rn(v.w - __half2float(h3));
    u64 hp = (u64)__half_as_ushort(h0)        | ((u64)__half_as_ushort(h1) << 16)
           | ((u64)__half_as_ushort(h2) << 32) | ((u64)__half_as_ushort(h3) << 48);
    u64 lp = (u64)__half_as_ushort(l0)        | ((u64)__half_as_ushort(l1) << 16)
           | ((u64)__half_as_ushort(l2) << 32) | ((u64)__half_as_ushort(l3) << 48);
    g_ext[(size_t)row * 64 + lane]      = hp;   // k 0..127  (hi)
    g_ext[(size_t)row * 64 + 32 + lane] = lp;   // k 128..255 (lo)
}

// ---------------------------------------------------------------------------
// main: mma.sync fp16 3-term GEMM (bitwise-identical per-dot arithmetic to
//       R10/R11), in-register top-3 with snapshot merge, double-buffered B
//       (CT=64) with cp.async issued before the MMA phase, 2 CTAs/SM.
// grid (32, 32), 256 threads, warp grid 2(m) x 4(n), warp tile 32x16.
// ---------------------------------------------------------------------------
__global__ __launch_bounds__(NT, 2)
void knn_mma_kernel(const float* __restrict__ X,
                    const float* __restrict__ strength,
                    float* __restrict__ Y) {
    extern __shared__ char smem[];
    const uint32_t sb = smem_u32(smem);
    const int tid  = threadIdx.x;
    const int wid  = tid >> 5;
    const int lane = tid & 31;
    const int b     = blockIdx.y;
    const int qbase = blockIdx.x * QT;
    const int xbase = b * N_;

    const uint4* E4 = reinterpret_cast<const uint4*>(g_ext);  // [row][32] 16B chunks
    float* mrgV = (float*)(smem + OFF_MRGV);
    int*   mrgI = (int*)(smem + OFF_MRGI);
    int*   sIdx = (int*)(smem + OFF_SIDX);

    // ---- async load A (query tile: 64 rows x 32 chunks) ----
    #pragma unroll
    for (int i = 0; i < 8; i++) {
        int li  = tid + i * NT;
        int row = li >> 5, cc = li & 31;
        cpasync16(sb + OFF_A + row * 512 + ((cc ^ (row & 7)) << 4),
                  &E4[(size_t)(xbase + qbase + row) * 32 + cc]);
    }
    // ---- async load B tile 0 (64 rows x 32 chunks) into buffer 0 ----
    #pragma unroll
    for (int i = 0; i < 8; i++) {
        int li  = tid + i * NT;
        int row = li >> 5, cc = li & 31;
        cpasync16(sb + OFF_B + row * 512 + ((cc ^ (row & 7)) << 4),
                  &E4[(size_t)(xbase + row) * 32 + cc]);
    }
    CP_COMMIT();

    // warp tile position and ldmatrix bases
    const int m0 = (wid & 1) * 32;          // 2 m-warps
    const int n0 = (wid >> 1) * 16;         // 4 n-warps, 16 cols each
    const int rowA = lane & 15;
    const int lcA  = lane >> 4;
    const int rowB = ((lane & 16) >> 1) + (lane & 7);
    const int lcB  = (lane >> 3) & 1;
    const uint32_t rc = (uint32_t)(lane & 7);

    uint32_t aBase[2];
    #pragma unroll
    for (int mi = 0; mi < 2; mi++)
        aBase[mi] = sb + OFF_A + (m0 + mi * 16 + rowA) * 512;

    // per-thread rows (4) and their top-3 lists
    const int rr   = lane >> 2;
    const int colb = (lane & 3) * 2;
    int Rl[4] = {m0 + rr, m0 + rr + 8, m0 + 16 + rr, m0 + 24 + rr};
    float tv[4][3];
    int   ti[4][3];
    #pragma unroll
    for (int r = 0; r < 4; r++) {
        tv[r][0] = tv[r][1] = tv[r][2] = 3.0e38f;
        ti[r][0] = ti[r][1] = ti[r][2] = 0;
    }

    CP_WAIT0();
    __syncthreads();   // A + B0 resident

    for (int ct = 0; ct < NTILE; ct++) {
        const int cb = ct & 1, nb = (ct + 1) & 1;

        // issue next B tile into the other buffer BEFORE the MMA phase;
        // it has the whole MMA phase to land. Buffer nb held tile ct-1,
        // fully consumed before the sync that ended iteration ct-1.
        if (ct < NTILE - 1) {
            const int nmb = (ct + 1) * CT;
            #pragma unroll
            for (int i = 0; i < 8; i++) {
                int li  = tid + i * NT;
                int row = li >> 5, cc = li & 31;
                cpasync16(sb + OFF_B + nb * 32768 + row * 512
                          + ((cc ^ (row & 7)) << 4),
                          &E4[(size_t)(xbase + nmb + row) * 32 + cc]);
            }
            CP_COMMIT();
        }

        // candidate sq for my 4 cols (2 per ni)
        float2 q[2];
        #pragma unroll
        for (int ni = 0; ni < 2; ni++)
            q[ni] = __ldg(reinterpret_cast<const float2*>(
                        g_sq + xbase + ct * CT + n0 + ni * 8 + colb));

        const uint32_t bBase = sb + OFF_B + cb * 32768 + (n0 + rowB) * 512;

        // ---- interleaved 3-term MMA: load fragments once per k ----
        float d[2][2][4];
        #pragma unroll
        for (int mi = 0; mi < 2; mi++)
            #pragma unroll
            for (int ni = 0; ni < 2; ni++)
                #pragma unroll
                for (int e = 0; e < 4; e++) d[mi][ni][e] = 0.f;

        #pragma unroll
        for (int k = 0; k < 8; k++) {
            const uint32_t chA = (uint32_t)(2 * k + lcA);
            const uint32_t chB = (uint32_t)(2 * k + lcB);
            uint32_t ah[2][4], al[2][4], bh[4], bl[4];
            #pragma unroll
            for (int mi = 0; mi < 2; mi++) {
                ldsm4(ah[mi][0], ah[mi][1], ah[mi][2], ah[mi][3],
                      aBase[mi] + ((chA ^ rc) << 4));
                ldsm4(al[mi][0], al[mi][1], al[mi][2], al[mi][3],
                      aBase[mi] + (((chA + 16) ^ rc) << 4));
            }
            ldsm4(bh[0], bh[1], bh[2], bh[3], bBase + ((chB ^ rc) << 4));
            ldsm4(bl[0], bl[1], bl[2], bl[3], bBase + (((chB + 16) ^ rc) << 4));

            #pragma unroll
            for (int mi = 0; mi < 2; mi++)
                #pragma unroll
                for (int ni = 0; ni < 2; ni++) {
                    uint32_t b0h = bh[ni * 2], b1h = bh[ni * 2 + 1];
                    uint32_t b0l = bl[ni * 2], b1l = bl[ni * 2 + 1];
                    mma16816(d[mi][ni][0], d[mi][ni][1], d[mi][ni][2], d[mi][ni][3],
                             ah[mi][0], ah[mi][1], ah[mi][2], ah[mi][3], b0h, b1h);
                    mma16816(d[mi][ni][0], d[mi][ni][1], d[mi][ni][2], d[mi][ni][3],
                             ah[mi][0], ah[mi][1], ah[mi][2], ah[mi][3], b0l, b1l);
                    mma16816(d[mi][ni][0], d[mi][ni][1], d[mi][ni][2], d[mi][ni][3],
                             al[mi][0], al[mi][1], al[mi][2], al[mi][3], b0h, b1h);
                }
        }

        // ---- in-register top-3 inserts (16 scores per thread) ----
        #pragma unroll
        for (int mi = 0; mi < 2; mi++)
            #pragma unroll
            for (int eh = 0; eh < 2; eh++) {
                const int ri  = mi * 2 + eh;
                const int ngl = qbase + Rl[ri];
                #pragma unroll
                for (int ni = 0; ni < 2; ni++) {
                    int   m  = ct * CT + n0 + ni * 8 + colb;
                    float s0 = fmaf(-2.f, d[mi][ni][eh * 2],     q[ni].x);
                    float s1 = fmaf(-2.f, d[mi][ni][eh * 2 + 1], q[ni].y);
                    if (m != ngl)     ins3(s0, m,     tv[ri], ti[ri]);
                    if (m + 1 != ngl) ins3(s1, m + 1, tv[ri], ti[ri]);
                }
            }

        CP_WAIT0();
        __syncthreads();   // B[ct+1] resident; everyone done with buffer cb
    }

    // ---- merge across the 4 lanes sharing each row: SNAPSHOT then insert ----
    #pragma unroll
    for (int off = 1; off <= 2; off <<= 1) {
        #pragma unroll
        for (int r = 0; r < 4; r++) {
            float sv[3]; int si[3];
            #pragma unroll
            for (int e = 0; e < 3; e++) {
                sv[e] = __shfl_xor_sync(0xffffffffu, tv[r][e], off);
                si[e] = __shfl_xor_sync(0xffffffffu, ti[r][e], off);
            }
            #pragma unroll
            for (int e = 0; e < 3; e++)
                ins3(sv[e], si[e], tv[r], ti[r]);
        }
    }
    // publish per-warp top-3 (4 n-warps per row)
    if ((lane & 3) == 0) {
        const int nw = wid >> 1;
        #pragma unroll
        for (int r = 0; r < 4; r++) {
            int base = (Rl[r] * 4 + nw) * 3;
            #pragma unroll
            for (int e = 0; e < 3; e++) {
                mrgV[base + e] = tv[r][e];
                mrgI[base + e] = ti[r][e];
            }
        }
    }
    __syncthreads();

    // final merge: one thread per row (sequential smem reads — no race)
    if (tid < QT) {
        float ft[3] = {3.0e38f, 3.0e38f, 3.0e38f};
        int   fi[3] = {0, 0, 0};
        #pragma unroll
        for (int nw = 0; nw < 4; nw++) {
            int base = (tid * 4 + nw) * 3;
            #pragma unroll
            for (int e = 0; e < 3; e++)
                ins3(mrgV[base + e], mrgI[base + e], ft, fi);
        }
        sIdx[tid * 3 + 0] = fi[0];
        sIdx[tid * 3 + 1] = fi[1];
        sIdx[tid * 3 + 2] = fi[2];
    }
    __syncthreads();

    // ---- gather + blend: (1-s)*x + (s/3)*(xa+xb+xc), original fp32 data ----
    float s  = fminf(fmaxf(strength[0], 0.f), 1.f);
    float w1 = 1.f - s;
    float w2 = s * (1.f / 3.f);
    const float4* X4 = reinterpret_cast<const float4*>(X + (size_t)b * N_ * D_);
    float* Yb = Y + (size_t)b * N_ * D_;
    for (int r = wid; r < QT; r += NT / 32) {
        int n  = qbase + r;
        int ia = sIdx[r * 3 + 0];
        int ib = sIdx[r * 3 + 1];
        int ic = sIdx[r * 3 + 2];
        float4 vn = X4[(size_t)n  * 32 + lane];
        float4 va = X4[(size_t)ia * 32 + lane];
        float4 vb = X4[(size_t)ib * 32 + lane];
        float4 vc = X4[(size_t)ic * 32 + lane];
        float4 o;
        o.x = w1 * vn.x + w2 * (va.x + vb.x + vc.x);
        o.y = w1 * vn.y + w2 * (va.y + vb.y + vc.y);
        o.z = w1 * vn.z + w2 * (va.z + vb.z + vc.z);
        o.w = w1 * vn.w + w2 * (va.w + vb.w + vc.w);
        reinterpret_cast<float4*>(Yb + (size_t)n * D_)[lane] = o;
    }
}

// ---------------------------------------------------------------------------
extern "C" void kernel_launch(void* const* d_in, const int* in_sizes, int n_in,
                              void* d_out, int out_size) {
    const float* X;
    const float* st;
    if (n_in >= 2 && in_sizes[0] == 1) { st = (const float*)d_in[0]; X = (const float*)d_in[1]; }
    else                               { X = (const float*)d_in[0]; st = (const float*)d_in[1]; }
    float* Y = (float*)d_out;

    int rows = B_ * N_;
    prep_kernel<<<(rows * 32 + 255) / 256, 256>>>(X);

    cudaFuncSetAttribute(knn_mma_kernel,
                         cudaFuncAttributeMaxDynamicSharedMemorySize, SMEM_TOTAL);
    dim3 grid(N_ / QT, B_);
    knn_mma_kernel<<<grid, NT, SMEM_TOTAL>>>(X, st, Y);
}

// round 13
// speedup vs baseline: 1.0572x; 1.0572x over previous
#include <cuda_runtime.h>
#include <cuda_fp16.h>
#include <cstdint>

// Problem constants (ParacrineCascade: B=32, N=2048, D=128, K=3)
#define B_     32
#define N_     2048
#define D_     128
#define QT     64                 // queries per CTA  (2 CTAs/SM)
#define CT     128                // candidates per tile
#define NTILE  (N_ / CT)          // 16
#define NT     256                // threads (8 warps: 2m x 4n, warp tile 32x32)

// smem byte offsets
#define OFF_A    0                // 32KB  query tile (64 rows x 512B)
#define OFF_B    32768            // 64KB: two 32KB group-private half-buffers
#define OFF_MRGV 98304            // 64*4*3 f32 = 3072
#define OFF_MRGI 101376           // 64*4*3 int = 3072
#define OFF_SIDX 104448           // 64*3 int = 768
#define SMEM_TOTAL 105472         // ~103KB -> 2 CTAs/SM

// device scratch (no cudaMalloc allowed)
__device__ float              g_sq [B_ * N_];
__device__ unsigned long long g_ext[(size_t)B_ * N_ * 64];  // [row][64] u64: hi(32)|lo(32)

typedef unsigned long long u64;

__device__ __forceinline__ uint32_t smem_u32(const void* p) {
    uint32_t a;
    asm("{ .reg .u64 t; cvta.to.shared.u64 t, %1; cvt.u32.u64 %0, t; }"
        : "=r"(a) : "l"(p));
    return a;
}
__device__ __forceinline__ void cpasync16(uint32_t dst, const void* src) {
    asm volatile("cp.async.cg.shared.global [%0], [%1], 16;" :: "r"(dst), "l"(src));
}
#define CP_COMMIT() asm volatile("cp.async.commit_group;" ::: "memory")
#define CP_WAIT0()  asm volatile("cp.async.wait_group 0;" ::: "memory")
#define GROUP_BAR(id) asm volatile("bar.sync %0, 128;" :: "r"(id) : "memory")

__device__ __forceinline__ void ldsm4(uint32_t& r0, uint32_t& r1,
                                      uint32_t& r2, uint32_t& r3, uint32_t addr) {
    asm volatile("ldmatrix.sync.aligned.m8n8.x4.shared.b16 {%0,%1,%2,%3}, [%4];"
                 : "=r"(r0), "=r"(r1), "=r"(r2), "=r"(r3) : "r"(addr));
}
__device__ __forceinline__ void mma16816(float& d0, float& d1, float& d2, float& d3,
                                         uint32_t a0, uint32_t a1, uint32_t a2, uint32_t a3,
                                         uint32_t b0, uint32_t b1) {
    asm volatile("mma.sync.aligned.m16n8k16.row.col.f32.f16.f16.f32 "
                 "{%0,%1,%2,%3}, {%4,%5,%6,%7}, {%8,%9}, {%0,%1,%2,%3};"
                 : "+f"(d0), "+f"(d1), "+f"(d2), "+f"(d3)
                 : "r"(a0), "r"(a1), "r"(a2), "r"(a3), "r"(b0), "r"(b1));
}

__device__ __forceinline__ void ins3(float s, int m, float* t, int* ix) {
    if (s < t[2]) {
        if (s < t[1]) {
            t[2] = t[1]; ix[2] = ix[1];
            if (s < t[0]) { t[1] = t[0]; ix[1] = ix[0]; t[0] = s; ix[0] = m; }
            else          { t[1] = s; ix[1] = m; }
        } else { t[2] = s; ix[2] = m; }
    }
}

// ---------------------------------------------------------------------------
// prep: squared norms (fp32) + fp16 hi/lo split -> g_ext. one warp per point.
// ---------------------------------------------------------------------------
__global__ void prep_kernel(const float* __restrict__ X) {
    int row  = (blockIdx.x * blockDim.x + threadIdx.x) >> 5;
    int lane = threadIdx.x & 31;
    if (row >= B_ * N_) return;
    float4 v = reinterpret_cast<const float4*>(X)[(size_t)row * 32 + lane];
    float s = v.x * v.x + v.y * v.y + v.z * v.z + v.w * v.w;
    #pragma unroll
    for (int off = 16; off; off >>= 1) s += __shfl_xor_sync(0xffffffffu, s, off);
    if (lane == 0) g_sq[row] = s;

    __half h0 = __float2half_rn(v.x), h1 = __float2half_rn(v.y);
    __half h2 = __float2half_rn(v.z), h3 = __float2half_rn(v.w);
    __half l0 = __float2half_rn(v.x - __half2float(h0));
    __half l1 = __float2half_rn(v.y - __half2float(h1));
    __half l2 = __float2half_rn(v.z - __half2float(h2));
    __half l3 = __float2half_rn(v.w - __half2float(h3));
    u64 hp = (u64)__half_as_ushort(h0)        | ((u64)__half_as_ushort(h1) << 16)
           | ((u64)__half_as_ushort(h2) << 32) | ((u64)__half_as_ushort(h3) << 48);
    u64 lp = (u64)__half_as_ushort(l0)        | ((u64)__half_as_ushort(l1) << 16)
           | ((u64)__half_as_ushort(l2) << 32) | ((u64)__half_as_ushort(l3) << 48);
    g_ext[(size_t)row * 64 + lane]      = hp;   // k 0..127  (hi)
    g_ext[(size_t)row * 64 + 32 + lane] = lp;   // k 128..255 (lo)
}

// ---------------------------------------------------------------------------
// main: mma.sync fp16 3-term GEMM (bitwise-identical per-dot arithmetic and
//       insert order to R11) with the CTA split into TWO independent 4-warp
//       groups: group g owns candidate rows [64g, 64g+64) of every tile in a
//       private 32KB buffer, loads it itself, and synchronizes only via a
//       group-scoped named barrier. 4 decoupled workers per SM hide each
//       other's load/epilogue phases.
// grid (32, 32), 256 threads, warp grid 2(m) x 4(n), warp tile 32x32.
// ---------------------------------------------------------------------------
__global__ __launch_bounds__(NT, 2)
void knn_mma_kernel(const float* __restrict__ X,
                    const float* __restrict__ strength,
                    float* __restrict__ Y) {
    extern __shared__ char smem[];
    const uint32_t sb = smem_u32(smem);
    const int tid  = threadIdx.x;
    const int wid  = tid >> 5;
    const int lane = tid & 31;
    const int b     = blockIdx.y;
    const int qbase = blockIdx.x * QT;
    const int xbase = b * N_;

    const int grp  = tid >> 7;            // 0: warps 0-3 (n0<64), 1: warps 4-7
    const int lt   = tid & 127;           // thread id within group
    const int barid = 1 + grp;

    const uint4* E4 = reinterpret_cast<const uint4*>(g_ext);  // [row][32] 16B chunks
    float* mrgV = (float*)(smem + OFF_MRGV);
    int*   mrgI = (int*)(smem + OFF_MRGI);
    int*   sIdx = (int*)(smem + OFF_SIDX);

    // ---- async load A (query tile: 64 rows x 32 chunks, all threads) ----
    #pragma unroll
    for (int i = 0; i < 8; i++) {
        int li  = tid + i * NT;
        int row = li >> 5, cc = li & 31;
        cpasync16(sb + OFF_A + row * 512 + ((cc ^ (row & 7)) << 4),
                  &E4[(size_t)(xbase + qbase + row) * 32 + cc]);
    }
    // ---- async load B tile 0: each group loads its 64-row half ----
    #pragma unroll
    for (int i = 0; i < 16; i++) {
        int c   = lt + i * 128;           // 0..2047: 64 rows x 32 chunks
        int row = c >> 5, cc = c & 31;
        cpasync16(sb + OFF_B + grp * 32768 + row * 512 + ((cc ^ (row & 7)) << 4),
                  &E4[(size_t)(xbase + grp * 64 + row) * 32 + cc]);
    }
    CP_COMMIT();

    // warp tile position and ldmatrix bases (identical geometry to R11)
    const int m0 = (wid & 1) * 32;          // 2 m-warps
    const int n0 = (wid >> 1) * 32;         // 4 n-warps (global col offset)
    const int rowA = lane & 15;
    const int lcA  = lane >> 4;
    const int rowB = ((lane & 16) >> 1) + (lane & 7);
    const int lcB  = (lane >> 3) & 1;
    const uint32_t rc = (uint32_t)(lane & 7);

    uint32_t aBase[2];
    #pragma unroll
    for (int mi = 0; mi < 2; mi++)
        aBase[mi] = sb + OFF_A + (m0 + mi * 16 + rowA) * 512;
    // group-local B base: local n offset = n0 - 64*grp  (in {0,32})
    uint32_t bBase[2];
    #pragma unroll
    for (int ni2 = 0; ni2 < 2; ni2++)
        bBase[ni2] = sb + OFF_B + grp * 32768
                   + (n0 - grp * 64 + ni2 * 16 + rowB) * 512;

    // per-thread rows (4) and their top-3 lists
    const int rr   = lane >> 2;
    const int colb = (lane & 3) * 2;
    int Rl[4] = {m0 + rr, m0 + rr + 8, m0 + 16 + rr, m0 + 24 + rr};
    float tv[4][3];
    int   ti[4][3];
    #pragma unroll
    for (int r = 0; r < 4; r++) {
        tv[r][0] = tv[r][1] = tv[r][2] = 3.0e38f;
        ti[r][0] = ti[r][1] = ti[r][2] = 0;
    }

    CP_WAIT0();
    __syncthreads();   // A + both B0 halves resident (one full sync at start)

    for (int ct = 0; ct < NTILE; ct++) {
        // candidate sq for my 8 cols
        float2 q[4];
        #pragma unroll
        for (int ni = 0; ni < 4; ni++)
            q[ni] = __ldg(reinterpret_cast<const float2*>(
                        g_sq + xbase + ct * CT + n0 + ni * 8 + colb));

        // ---- interleaved 3-term MMA: load fragments once per k ----
        float d[2][4][4];
        #pragma unroll
        for (int mi = 0; mi < 2; mi++)
            #pragma unroll
            for (int ni = 0; ni < 4; ni++)
                #pragma unroll
                for (int e = 0; e < 4; e++) d[mi][ni][e] = 0.f;

        #pragma unroll
        for (int k = 0; k < 8; k++) {
            const uint32_t chA = (uint32_t)(2 * k + lcA);
            const uint32_t chB = (uint32_t)(2 * k + lcB);
            uint32_t ah[2][4], al[2][4], bh[2][4], bl[2][4];
            #pragma unroll
            for (int mi = 0; mi < 2; mi++) {
                ldsm4(ah[mi][0], ah[mi][1], ah[mi][2], ah[mi][3],
                      aBase[mi] + ((chA ^ rc) << 4));
                ldsm4(al[mi][0], al[mi][1], al[mi][2], al[mi][3],
                      aBase[mi] + (((chA + 16) ^ rc) << 4));
            }
            #pragma unroll
            for (int ni2 = 0; ni2 < 2; ni2++) {
                ldsm4(bh[ni2][0], bh[ni2][1], bh[ni2][2], bh[ni2][3],
                      bBase[ni2] + ((chB ^ rc) << 4));
                ldsm4(bl[ni2][0], bl[ni2][1], bl[ni2][2], bl[ni2][3],
                      bBase[ni2] + (((chB + 16) ^ rc) << 4));
            }
            #pragma unroll
            for (int mi = 0; mi < 2; mi++)
                #pragma unroll
                for (int ni = 0; ni < 4; ni++) {
                    uint32_t b0h = bh[ni >> 1][(ni & 1) * 2];
                    uint32_t b1h = bh[ni >> 1][(ni & 1) * 2 + 1];
                    uint32_t b0l = bl[ni >> 1][(ni & 1) * 2];
                    uint32_t b1l = bl[ni >> 1][(ni & 1) * 2 + 1];
                    mma16816(d[mi][ni][0], d[mi][ni][1], d[mi][ni][2], d[mi][ni][3],
                             ah[mi][0], ah[mi][1], ah[mi][2], ah[mi][3], b0h, b1h);
                    mma16816(d[mi][ni][0], d[mi][ni][1], d[mi][ni][2], d[mi][ni][3],
                             ah[mi][0], ah[mi][1], ah[mi][2], ah[mi][3], b0l, b1l);
                    mma16816(d[mi][ni][0], d[mi][ni][1], d[mi][ni][2], d[mi][ni][3],
                             al[mi][0], al[mi][1], al[mi][2], al[mi][3], b0h, b1h);
                }
        }

        GROUP_BAR(barid);   // my group done reading its half-buffer

        // issue next half-tile for MY group (overlaps epilogue + drifts
        // against the other group / co-resident CTA)
        if (ct < NTILE - 1) {
            const int nmb = (ct + 1) * CT + grp * 64;
            #pragma unroll
            for (int i = 0; i < 16; i++) {
                int c   = lt + i * 128;
                int row = c >> 5, cc = c & 31;
                cpasync16(sb + OFF_B + grp * 32768 + row * 512
                          + ((cc ^ (row & 7)) << 4),
                          &E4[(size_t)(xbase + nmb + row) * 32 + cc]);
            }
            CP_COMMIT();
        }

        // ---- in-register top-3 inserts (32 scores per thread) ----
        #pragma unroll
        for (int mi = 0; mi < 2; mi++)
            #pragma unroll
            for (int eh = 0; eh < 2; eh++) {
                const int ri  = mi * 2 + eh;
                const int ngl = qbase + Rl[ri];
                #pragma unroll
                for (int ni = 0; ni < 4; ni++) {
                    int   m  = ct * CT + n0 + ni * 8 + colb;
                    float s0 = fmaf(-2.f, d[mi][ni][eh * 2],     q[ni].x);
                    float s1 = fmaf(-2.f, d[mi][ni][eh * 2 + 1], q[ni].y);
                    if (m != ngl)     ins3(s0, m,     tv[ri], ti[ri]);
                    if (m + 1 != ngl) ins3(s1, m + 1, tv[ri], ti[ri]);
                }
            }

        CP_WAIT0();
        GROUP_BAR(barid);   // my group's next half-tile resident
    }

    // ---- merge across the 4 lanes sharing each row: SNAPSHOT then insert ----
    #pragma unroll
    for (int off = 1; off <= 2; off <<= 1) {
        #pragma unroll
        for (int r = 0; r < 4; r++) {
            float sv[3]; int si[3];
            #pragma unroll
            for (int e = 0; e < 3; e++) {
                sv[e] = __shfl_xor_sync(0xffffffffu, tv[r][e], off);
                si[e] = __shfl_xor_sync(0xffffffffu, ti[r][e], off);
            }
            #pragma unroll
            for (int e = 0; e < 3; e++)
                ins3(sv[e], si[e], tv[r], ti[r]);
        }
    }
    // publish per-warp top-3 (4 n-warps per row)
    if ((lane & 3) == 0) {
        const int nw = wid >> 1;
        #pragma unroll
        for (int r = 0; r < 4; r++) {
            int base = (Rl[r] * 4 + nw) * 3;
            #pragma unroll
            for (int e = 0; e < 3; e++) {
                mrgV[base + e] = tv[r][e];
                mrgI[base + e] = ti[r][e];
            }
        }
    }
    __syncthreads();

    // final merge: one thread per row (ascending nw = ascending candidate
    // ranges -> tie behavior identical to sequential processing)
    if (tid < QT) {
        float ft[3] = {3.0e38f, 3.0e38f, 3.0e38f};
        int   fi[3] = {0, 0, 0};
        #pragma unroll
        for (int nw = 0; nw < 4; nw++) {
            int base = (tid * 4 + nw) * 3;
            #pragma unroll
            for (int e = 0; e < 3; e++)
                ins3(mrgV[base + e], mrgI[base + e], ft, fi);
        }
        sIdx[tid * 3 + 0] = fi[0];
        sIdx[tid * 3 + 1] = fi[1];
        sIdx[tid * 3 + 2] = fi[2];
    }
    __syncthreads();

    // ---- gather + blend: (1-s)*x + (s/3)*(xa+xb+xc), original fp32 data ----
    float s  = fminf(fmaxf(strength[0], 0.f), 1.f);
    float w1 = 1.f - s;
    float w2 = s * (1.f / 3.f);
    const float4* X4 = reinterpret_cast<const float4*>(X + (size_t)b * N_ * D_);
    float* Yb = Y + (size_t)b * N_ * D_;
    for (int r = wid; r < QT; r += NT / 32) {
        int n  = qbase + r;
        int ia = sIdx[r * 3 + 0];
        int ib = sIdx[r * 3 + 1];
        int ic = sIdx[r * 3 + 2];
        float4 vn = X4[(size_t)n  * 32 + lane];
        float4 va = X4[(size_t)ia * 32 + lane];
        float4 vb = X4[(size_t)ib * 32 + lane];
        float4 vc = X4[(size_t)ic * 32 + lane];
        float4 o;
        o.x = w1 * vn.x + w2 * (va.x + vb.x + vc.x);
        o.y = w1 * vn.y + w2 * (va.y + vb.y + vc.y);
        o.z = w1 * vn.z + w2 * (va.z + vb.z + vc.z);
        o.w = w1 * vn.w + w2 * (va.w + vb.w + vc.w);
        reinterpret_cast<float4*>(Yb + (size_t)n * D_)[lane] = o;
    }
}

// ---------------------------------------------------------------------------
extern "C" void kernel_launch(void* const* d_in, const int* in_sizes, int n_in,
                              void* d_out, int out_size) {
    const float* X;
    const float* st;
    if (n_in >= 2 && in_sizes[0] == 1) { st = (const float*)d_in[0]; X = (const float*)d_in[1]; }
    else                               { X = (const float*)d_in[0]; st = (const float*)d_in[1]; }
    float* Y = (float*)d_out;

    int rows = B_ * N_;
    prep_kernel<<<(rows * 32 + 255) / 256, 256>>>(X);

    cudaFuncSetAttribute(knn_mma_kernel,
                         cudaFuncAttributeMaxDynamicSharedMemorySize, SMEM_TOTAL);
    dim3 grid(N_ / QT, B_);
    knn_mma_kernel<<<grid, NT, SMEM_TOTAL>>>(X, st, Y);
}

// round 14
// speedup vs baseline: 1.0701x; 1.0122x over previous
#include <cuda_runtime.h>
#include <cuda_fp16.h>
#include <cstdint>

// Problem constants (ParacrineCascade: B=32, N=2048, D=128, K=3)
#define B_     32
#define N_     2048
#define D_     128
#define QT     64                 // queries per CTA  (2 CTAs/SM)
#define CT     128                // candidates per tile
#define NTILE  (N_ / CT)          // 16
#define NT     256                // threads (8 warps: 2m x 4n, warp tile 32x32)

// smem byte offsets
#define OFF_A    0                // 32KB  query tile (64 rows x 512B)
#define OFF_B    32768            // 64KB: two 32KB group-private half-buffers
#define OFF_MRGV 98304            // 64*4*3 f32 = 3072
#define OFF_MRGI 101376           // 64*4*3 int = 3072
#define OFF_SIDX 104448           // 64*3 int = 768
#define SMEM_TOTAL 105472         // ~103KB -> 2 CTAs/SM

// device scratch (no cudaMalloc allowed)
__device__ float              g_sq [B_ * N_];
__device__ unsigned long long g_ext[(size_t)B_ * N_ * 64];  // [row][64] u64: hi(32)|lo(32)

typedef unsigned long long u64;

__device__ __forceinline__ uint32_t smem_u32(const void* p) {
    uint32_t a;
    asm("{ .reg .u64 t; cvta.to.shared.u64 t, %1; cvt.u32.u64 %0, t; }"
        : "=r"(a) : "l"(p));
    return a;
}
__device__ __forceinline__ void cpasync16(uint32_t dst, const void* src) {
    asm volatile("cp.async.cg.shared.global [%0], [%1], 16;" :: "r"(dst), "l"(src));
}
#define CP_COMMIT() asm volatile("cp.async.commit_group;" ::: "memory")
#define CP_WAIT0()  asm volatile("cp.async.wait_group 0;" ::: "memory")
#define GROUP_BAR(id) asm volatile("bar.sync %0, 128;" :: "r"(id) : "memory")

__device__ __forceinline__ void ldsm4(uint32_t& r0, uint32_t& r1,
                                      uint32_t& r2, uint32_t& r3, uint32_t addr) {
    asm volatile("ldmatrix.sync.aligned.m8n8.x4.shared.b16 {%0,%1,%2,%3}, [%4];"
                 : "=r"(r0), "=r"(r1), "=r"(r2), "=r"(r3) : "r"(addr));
}
__device__ __forceinline__ void mma16816(float& d0, float& d1, float& d2, float& d3,
                                         uint32_t a0, uint32_t a1, uint32_t a2, uint32_t a3,
                                         uint32_t b0, uint32_t b1) {
    asm volatile("mma.sync.aligned.m16n8k16.row.col.f32.f16.f16.f32 "
                 "{%0,%1,%2,%3}, {%4,%5,%6,%7}, {%8,%9}, {%0,%1,%2,%3};"
                 : "+f"(d0), "+f"(d1), "+f"(d2), "+f"(d3)
                 : "r"(a0), "r"(a1), "r"(a2), "r"(a3), "r"(b0), "r"(b1));
}

__device__ __forceinline__ void ins3(float s, int m, float* t, int* ix) {
    if (s < t[2]) {
        if (s < t[1]) {
            t[2] = t[1]; ix[2] = ix[1];
            if (s < t[0]) { t[1] = t[0]; ix[1] = ix[0]; t[0] = s; ix[0] = m; }
            else          { t[1] = s; ix[1] = m; }
        } else { t[2] = s; ix[2] = m; }
    }
}

// ---------------------------------------------------------------------------
// prep: squared norms (fp32) + fp16 hi/lo split -> g_ext. one warp per point.
// ---------------------------------------------------------------------------
__global__ void prep_kernel(const float* __restrict__ X) {
    int row  = (blockIdx.x * blockDim.x + threadIdx.x) >> 5;
    int lane = threadIdx.x & 31;
    if (row >= B_ * N_) return;
    float4 v = reinterpret_cast<const float4*>(X)[(size_t)row * 32 + lane];
    float s = v.x * v.x + v.y * v.y + v.z * v.z + v.w * v.w;
    #pragma unroll
    for (int off = 16; off; off >>= 1) s += __shfl_xor_sync(0xffffffffu, s, off);
    if (lane == 0) g_sq[row] = s;

    __half h0 = __float2half_rn(v.x), h1 = __float2half_rn(v.y);
    __half h2 = __float2half_rn(v.z), h3 = __float2half_rn(v.w);
    __half l0 = __float2half_rn(v.x - __half2float(h0));
    __half l1 = __float2half_rn(v.y - __half2float(h1));
    __half l2 = __float2half_rn(v.z - __half2float(h2));
    __half l3 = __float2half_rn(v.w - __half2float(h3));
    u64 hp = (u64)__half_as_ushort(h0)        | ((u64)__half_as_ushort(h1) << 16)
           | ((u64)__half_as_ushort(h2) << 32) | ((u64)__half_as_ushort(h3) << 48);
    u64 lp = (u64)__half_as_ushort(l0)        | ((u64)__half_as_ushort(l1) << 16)
           | ((u64)__half_as_ushort(l2) << 32) | ((u64)__half_as_ushort(l3) << 48);
    g_ext[(size_t)row * 64 + lane]      = hp;   // k 0..127  (hi)
    g_ext[(size_t)row * 64 + 32 + lane] = lp;   // k 128..255 (lo)
}

// ---------------------------------------------------------------------------
// main: mma.sync fp16 3-term GEMM (bitwise-identical per-dot arithmetic and
//       insert order to R13), two independent 4-warp groups per CTA with
//       group-private half-buffers and named barriers. R14: diagonal-tile
//       specialization (self-exclusion check only in the one tile that can
//       contain it) + halved swizzle address math in the k-loop.
// grid (32, 32), 256 threads, warp grid 2(m) x 4(n), warp tile 32x32.
// ---------------------------------------------------------------------------
__global__ __launch_bounds__(NT, 2)
void knn_mma_kernel(const float* __restrict__ X,
                    const float* __restrict__ strength,
                    float* __restrict__ Y) {
    extern __shared__ char smem[];
    const uint32_t sb = smem_u32(smem);
    const int tid  = threadIdx.x;
    const int wid  = tid >> 5;
    const int lane = tid & 31;
    const int b     = blockIdx.y;
    const int qbase = blockIdx.x * QT;
    const int xbase = b * N_;
    const int diagTile = blockIdx.x >> 1;   // the only tile containing m==n

    const int grp  = tid >> 7;            // 0: warps 0-3 (n0<64), 1: warps 4-7
    const int lt   = tid & 127;           // thread id within group
    const int barid = 1 + grp;

    const uint4* E4 = reinterpret_cast<const uint4*>(g_ext);  // [row][32] 16B chunks
    float* mrgV = (float*)(smem + OFF_MRGV);
    int*   mrgI = (int*)(smem + OFF_MRGI);
    int*   sIdx = (int*)(smem + OFF_SIDX);

    // ---- async load A (query tile: 64 rows x 32 chunks, all threads) ----
    #pragma unroll
    for (int i = 0; i < 8; i++) {
        int li  = tid + i * NT;
        int row = li >> 5, cc = li & 31;
        cpasync16(sb + OFF_A + row * 512 + ((cc ^ (row & 7)) << 4),
                  &E4[(size_t)(xbase + qbase + row) * 32 + cc]);
    }
    // ---- async load B tile 0: each group loads its 64-row half ----
    #pragma unroll
    for (int i = 0; i < 16; i++) {
        int c   = lt + i * 128;           // 0..2047: 64 rows x 32 chunks
        int row = c >> 5, cc = c & 31;
        cpasync16(sb + OFF_B + grp * 32768 + row * 512 + ((cc ^ (row & 7)) << 4),
                  &E4[(size_t)(xbase + grp * 64 + row) * 32 + cc]);
    }
    CP_COMMIT();

    // warp tile position and ldmatrix bases (identical geometry to R13)
    const int m0 = (wid & 1) * 32;          // 2 m-warps
    const int n0 = (wid >> 1) * 32;         // 4 n-warps (global col offset)
    const int rowA = lane & 15;
    const int lcA  = lane >> 4;
    const int rowB = ((lane & 16) >> 1) + (lane & 7);
    const int lcB  = (lane >> 3) & 1;
    const uint32_t rc = (uint32_t)(lane & 7);

    uint32_t aBase[2];
    #pragma unroll
    for (int mi = 0; mi < 2; mi++)
        aBase[mi] = sb + OFF_A + (m0 + mi * 16 + rowA) * 512;
    // group-local B base: local n offset = n0 - 64*grp  (in {0,32})
    uint32_t bBase[2];
    #pragma unroll
    for (int ni2 = 0; ni2 < 2; ni2++)
        bBase[ni2] = sb + OFF_B + grp * 32768
                   + (n0 - grp * 64 + ni2 * 16 + rowB) * 512;

    // per-thread rows (4) and their top-3 lists
    const int rr   = lane >> 2;
    const int colb = (lane & 3) * 2;
    int Rl[4] = {m0 + rr, m0 + rr + 8, m0 + 16 + rr, m0 + 24 + rr};
    float tv[4][3];
    int   ti[4][3];
    #pragma unroll
    for (int r = 0; r < 4; r++) {
        tv[r][0] = tv[r][1] = tv[r][2] = 3.0e38f;
        ti[r][0] = ti[r][1] = ti[r][2] = 0;
    }

    CP_WAIT0();
    __syncthreads();   // A + both B0 halves resident (one full sync at start)

    for (int ct = 0; ct < NTILE; ct++) {
        // candidate sq for my 8 cols
        float2 q[4];
        #pragma unroll
        for (int ni = 0; ni < 4; ni++)
            q[ni] = __ldg(reinterpret_cast<const float2*>(
                        g_sq + xbase + ct * CT + n0 + ni * 8 + colb));

        // ---- interleaved 3-term MMA: load fragments once per k ----
        float d[2][4][4];
        #pragma unroll
        for (int mi = 0; mi < 2; mi++)
            #pragma unroll
            for (int ni = 0; ni < 4; ni++)
                #pragma unroll
                for (int e = 0; e < 4; e++) d[mi][ni][e] = 0.f;

        #pragma unroll
        for (int k = 0; k < 8; k++) {
            // (ch+16)^rc == (ch^rc)+16 since rc<8 -> lo-fragment addr = +256B
            const uint32_t offA = (((uint32_t)(2 * k + lcA) ^ rc) << 4);
            const uint32_t offB = (((uint32_t)(2 * k + lcB) ^ rc) << 4);
            uint32_t ah[2][4], al[2][4], bh[2][4], bl[2][4];
            #pragma unroll
            for (int mi = 0; mi < 2; mi++) {
                ldsm4(ah[mi][0], ah[mi][1], ah[mi][2], ah[mi][3],
                      aBase[mi] + offA);
                ldsm4(al[mi][0], al[mi][1], al[mi][2], al[mi][3],
                      aBase[mi] + offA + 256);
            }
            #pragma unroll
            for (int ni2 = 0; ni2 < 2; ni2++) {
                ldsm4(bh[ni2][0], bh[ni2][1], bh[ni2][2], bh[ni2][3],
                      bBase[ni2] + offB);
                ldsm4(bl[ni2][0], bl[ni2][1], bl[ni2][2], bl[ni2][3],
                      bBase[ni2] + offB + 256);
            }
            #pragma unroll
            for (int mi = 0; mi < 2; mi++)
                #pragma unroll
                for (int ni = 0; ni < 4; ni++) {
                    uint32_t b0h = bh[ni >> 1][(ni & 1) * 2];
                    uint32_t b1h = bh[ni >> 1][(ni & 1) * 2 + 1];
                    uint32_t b0l = bl[ni >> 1][(ni & 1) * 2];
                    uint32_t b1l = bl[ni >> 1][(ni & 1) * 2 + 1];
                    mma16816(d[mi][ni][0], d[mi][ni][1], d[mi][ni][2], d[mi][ni][3],
                             ah[mi][0], ah[mi][1], ah[mi][2], ah[mi][3], b0h, b1h);
                    mma16816(d[mi][ni][0], d[mi][ni][1], d[mi][ni][2], d[mi][ni][3],
                             ah[mi][0], ah[mi][1], ah[mi][2], ah[mi][3], b0l, b1l);
                    mma16816(d[mi][ni][0], d[mi][ni][1], d[mi][ni][2], d[mi][ni][3],
                             al[mi][0], al[mi][1], al[mi][2], al[mi][3], b0h, b1h);
                }
        }

        GROUP_BAR(barid);   // my group done reading its half-buffer

        // issue next half-tile for MY group (overlaps epilogue + drifts
        // against the other group / co-resident CTA)
        if (ct < NTILE - 1) {
            const int nmb = (ct + 1) * CT + grp * 64;
            #pragma unroll
            for (int i = 0; i < 16; i++) {
                int c   = lt + i * 128;
                int row = c >> 5, cc = c & 31;
                cpasync16(sb + OFF_B + grp * 32768 + row * 512
                          + ((cc ^ (row & 7)) << 4),
                          &E4[(size_t)(xbase + nmb + row) * 32 + cc]);
            }
            CP_COMMIT();
        }

        // ---- in-register top-3 inserts (32 scores per thread) ----
        // self-exclusion only possible in the diagonal tile; elsewhere the
        // m != ngl predicate is provably true -> drop it (identical result).
        if (ct == diagTile) {
            #pragma unroll
            for (int mi = 0; mi < 2; mi++)
                #pragma unroll
                for (int eh = 0; eh < 2; eh++) {
                    const int ri  = mi * 2 + eh;
                    const int ngl = qbase + Rl[ri];
                    #pragma unroll
                    for (int ni = 0; ni < 4; ni++) {
                        int   m  = ct * CT + n0 + ni * 8 + colb;
                        float s0 = fmaf(-2.f, d[mi][ni][eh * 2],     q[ni].x);
                        float s1 = fmaf(-2.f, d[mi][ni][eh * 2 + 1], q[ni].y);
                        if (m != ngl)     ins3(s0, m,     tv[ri], ti[ri]);
                        if (m + 1 != ngl) ins3(s1, m + 1, tv[ri], ti[ri]);
                    }
                }
        } else {
            const int mb0 = ct * CT + n0 + colb;
            #pragma unroll
            for (int mi = 0; mi < 2; mi++)
                #pragma unroll
                for (int eh = 0; eh < 2; eh++) {
                    const int ri = mi * 2 + eh;
                    #pragma unroll
                    for (int ni = 0; ni < 4; ni++) {
                        int   m  = mb0 + ni * 8;
                        float s0 = fmaf(-2.f, d[mi][ni][eh * 2],     q[ni].x);
                        float s1 = fmaf(-2.f, d[mi][ni][eh * 2 + 1], q[ni].y);
                        ins3(s0, m,     tv[ri], ti[ri]);
                        ins3(s1, m + 1, tv[ri], ti[ri]);
                    }
                }
        }

        CP_WAIT0();
        GROUP_BAR(barid);   // my group's next half-tile resident
    }

    // ---- merge across the 4 lanes sharing each row: SNAPSHOT then insert ----
    #pragma unroll
    for (int off = 1; off <= 2; off <<= 1) {
        #pragma unroll
        for (int r = 0; r < 4; r++) {
            float sv[3]; int si[3];
            #pragma unroll
            for (int e = 0; e < 3; e++) {
                sv[e] = __shfl_xor_sync(0xffffffffu, tv[r][e], off);
                si[e] = __shfl_xor_sync(0xffffffffu, ti[r][e], off);
            }
            #pragma unroll
            for (int e = 0; e < 3; e++)
                ins3(sv[e], si[e], tv[r], ti[r]);
        }
    }
    // publish per-warp top-3 (4 n-warps per row)
    if ((lane & 3) == 0) {
        const int nw = wid >> 1;
        #pragma unroll
        for (int r = 0; r < 4; r++) {
            int base = (Rl[r] * 4 + nw) * 3;
            #pragma unroll
            for (int e = 0; e < 3; e++) {
                mrgV[base + e] = tv[r][e];
                mrgI[base + e] = ti[r][e];
            }
        }
    }
    __syncthreads();

    // final merge: one thread per row (ascending nw = ascending candidate
    // ranges -> tie behavior identical to sequential processing)
    if (tid < QT) {
        float ft[3] = {3.0e38f, 3.0e38f, 3.0e38f};
        int   fi[3] = {0, 0, 0};
        #pragma unroll
        for (int nw = 0; nw < 4; nw++) {
            int base = (tid * 4 + nw) * 3;
            #pragma unroll
            for (int e = 0; e < 3; e++)
                ins3(mrgV[base + e], mrgI[base + e], ft, fi);
        }
        sIdx[tid * 3 + 0] = fi[0];
        sIdx[tid * 3 + 1] = fi[1];
        sIdx[tid * 3 + 2] = fi[2];
    }
    __syncthreads();

    // ---- gather + blend: (1-s)*x + (s/3)*(xa+xb+xc), original fp32 data ----
    float s  = fminf(fmaxf(strength[0], 0.f), 1.f);
    float w1 = 1.f - s;
    float w2 = s * (1.f / 3.f);
    const float4* X4 = reinterpret_cast<const float4*>(X + (size_t)b * N_ * D_);
    float* Yb = Y + (size_t)b * N_ * D_;
    for (int r = wid; r < QT; r += NT / 32) {
        int n  = qbase + r;
        int ia = sIdx[r * 3 + 0];
        int ib = sIdx[r * 3 + 1];
        int ic = sIdx[r * 3 + 2];
        float4 vn = X4[(size_t)n  * 32 + lane];
        float4 va = X4[(size_t)ia * 32 + lane];
        float4 vb = X4[(size_t)ib * 32 + lane];
        float4 vc = X4[(size_t)ic * 32 + lane];
        float4 o;
        o.x = w1 * vn.x + w2 * (va.x + vb.x + vc.x);
        o.y = w1 * vn.y + w2 * (va.y + vb.y + vc.y);
        o.z = w1 * vn.z + w2 * (va.z + vb.z + vc.z);
        o.w = w1 * vn.w + w2 * (va.w + vb.w + vc.w);
        reinterpret_cast<float4*>(Yb + (size_t)n * D_)[lane] = o;
    }
}

// ---------------------------------------------------------------------------
extern "C" void kernel_launch(void* const* d_in, const int* in_sizes, int n_in,
                              void* d_out, int out_size) {
    const float* X;
    const float* st;
    if (n_in >= 2 && in_sizes[0] == 1) { st = (const float*)d_in[0]; X = (const float*)d_in[1]; }
    else                               { X = (const float*)d_in[0]; st = (const float*)d_in[1]; }
    float* Y = (float*)d_out;

    int rows = B_ * N_;
    prep_kernel<<<(rows * 32 + 255) / 256, 256>>>(X);

    cudaFuncSetAttribute(knn_mma_kernel,
                         cudaFuncAttributeMaxDynamicSharedMemorySize, SMEM_TOTAL);
    dim3 grid(N_ / QT, B_);
    knn_mma_kernel<<<grid, NT, SMEM_TOTAL>>>(X, st, Y);
}

// round 15
// speedup vs baseline: 1.0729x; 1.0026x over previous
#include <cuda_runtime.h>
#include <cuda_fp16.h>
#include <cstdint>

// Problem constants (ParacrineCascade: B=32, N=2048, D=128, K=3)
#define B_     32
#define N_     2048
#define D_     128
#define QT     64                 // queries per CTA  (2 CTAs/SM)
#define CT     128                // candidates per tile
#define NTILE  (N_ / CT)          // 16
#define NT     256                // threads (8 warps: 2m x 4n, warp tile 32x32)

// smem byte offsets
#define OFF_A    0                // 32KB  query tile (64 rows x 512B)
#define OFF_B    32768            // 64KB: two 32KB group-private half-buffers
#define OFF_MRGV 98304            // 64*4*3 f32 = 3072
#define OFF_MRGI 101376           // 64*4*3 int = 3072
#define OFF_SIDX 104448           // 64*3 int = 768
#define SMEM_TOTAL 105472         // ~103KB -> 2 CTAs/SM

// device scratch (no cudaMalloc allowed)
__device__ float              g_sq [B_ * N_];
__device__ unsigned long long g_ext[(size_t)B_ * N_ * 64];  // [row][64] u64: hi(32)|lo(32)

typedef unsigned long long u64;

__device__ __forceinline__ uint32_t smem_u32(const void* p) {
    uint32_t a;
    asm("{ .reg .u64 t; cvta.to.shared.u64 t, %1; cvt.u32.u64 %0, t; }"
        : "=r"(a) : "l"(p));
    return a;
}
__device__ __forceinline__ void cpasync16(uint32_t dst, const void* src) {
    asm volatile("cp.async.cg.shared.global [%0], [%1], 16;" :: "r"(dst), "l"(src));
}
#define CP_COMMIT() asm volatile("cp.async.commit_group;" ::: "memory")
#define CP_WAIT0()  asm volatile("cp.async.wait_group 0;" ::: "memory")
#define GROUP_BAR(id) asm volatile("bar.sync %0, 128;" :: "r"(id) : "memory")

__device__ __forceinline__ void ldsm4(uint32_t& r0, uint32_t& r1,
                                      uint32_t& r2, uint32_t& r3, uint32_t addr) {
    asm volatile("ldmatrix.sync.aligned.m8n8.x4.shared.b16 {%0,%1,%2,%3}, [%4];"
                 : "=r"(r0), "=r"(r1), "=r"(r2), "=r"(r3) : "r"(addr));
}
__device__ __forceinline__ void mma16816(float& d0, float& d1, float& d2, float& d3,
                                         uint32_t a0, uint32_t a1, uint32_t a2, uint32_t a3,
                                         uint32_t b0, uint32_t b1) {
    asm volatile("mma.sync.aligned.m16n8k16.row.col.f32.f16.f16.f32 "
                 "{%0,%1,%2,%3}, {%4,%5,%6,%7}, {%8,%9}, {%0,%1,%2,%3};"
                 : "+f"(d0), "+f"(d1), "+f"(d2), "+f"(d3)
                 : "r"(a0), "r"(a1), "r"(a2), "r"(a3), "r"(b0), "r"(b1));
}

__device__ __forceinline__ void ins3(float s, int m, float* t, int* ix) {
    if (s < t[2]) {
        if (s < t[1]) {
            t[2] = t[1]; ix[2] = ix[1];
            if (s < t[0]) { t[1] = t[0]; ix[1] = ix[0]; t[0] = s; ix[0] = m; }
            else          { t[1] = s; ix[1] = m; }
        } else { t[2] = s; ix[2] = m; }
    }
}

// ---------------------------------------------------------------------------
// prep: squared norms (fp32) + fp16 hi/lo split -> g_ext. one warp per point.
// ---------------------------------------------------------------------------
__global__ void prep_kernel(const float* __restrict__ X) {
    int row  = (blockIdx.x * blockDim.x + threadIdx.x) >> 5;
    int lane = threadIdx.x & 31;
    if (row >= B_ * N_) return;
    float4 v = reinterpret_cast<const float4*>(X)[(size_t)row * 32 + lane];
    float s = v.x * v.x + v.y * v.y + v.z * v.z + v.w * v.w;
    #pragma unroll
    for (int off = 16; off; off >>= 1) s += __shfl_xor_sync(0xffffffffu, s, off);
    if (lane == 0) g_sq[row] = s;

    __half h0 = __float2half_rn(v.x), h1 = __float2half_rn(v.y);
    __half h2 = __float2half_rn(v.z), h3 = __float2half_rn(v.w);
    __half l0 = __float2half_rn(v.x - __half2float(h0));
    __half l1 = __float2half_rn(v.y - __half2float(h1));
    __half l2 = __float2half_rn(v.z - __half2float(h2));
    __half l3 = __float2half_rn(v.w - __half2float(h3));
    u64 hp = (u64)__half_as_ushort(h0)        | ((u64)__half_as_ushort(h1) << 16)
           | ((u64)__half_as_ushort(h2) << 32) | ((u64)__half_as_ushort(h3) << 48);
    u64 lp = (u64)__half_as_ushort(l0)        | ((u64)__half_as_ushort(l1) << 16)
           | ((u64)__half_as_ushort(l2) << 32) | ((u64)__half_as_ushort(l3) << 48);
    g_ext[(size_t)row * 64 + lane]      = hp;   // k 0..127  (hi)
    g_ext[(size_t)row * 64 + 32 + lane] = lp;   // k 128..255 (lo)
}

// ---------------------------------------------------------------------------
// main: mma.sync fp16 3-term GEMM, two independent 4-warp groups per CTA.
// R15: phase-split MMA issue (hh burst covers al/bl LDSM latency).
// Per-accumulator order stays hh->hl->lh -> scores bitwise-identical to R14.
// grid (32, 32), 256 threads, warp grid 2(m) x 4(n), warp tile 32x32.
// ---------------------------------------------------------------------------
__global__ __launch_bounds__(NT, 2)
void knn_mma_kernel(const float* __restrict__ X,
                    const float* __restrict__ strength,
                    float* __restrict__ Y) {
    extern __shared__ char smem[];
    const uint32_t sb = smem_u32(smem);
    const int tid  = threadIdx.x;
    const int wid  = tid >> 5;
    const int lane = tid & 31;
    const int b     = blockIdx.y;
    const int qbase = blockIdx.x * QT;
    const int xbase = b * N_;
    const int diagTile = blockIdx.x >> 1;   // the only tile containing m==n

    const int grp  = tid >> 7;            // 0: warps 0-3 (n0<64), 1: warps 4-7
    const int lt   = tid & 127;           // thread id within group
    const int barid = 1 + grp;

    const uint4* E4 = reinterpret_cast<const uint4*>(g_ext);  // [row][32] 16B chunks
    float* mrgV = (float*)(smem + OFF_MRGV);
    int*   mrgI = (int*)(smem + OFF_MRGI);
    int*   sIdx = (int*)(smem + OFF_SIDX);

    // ---- async load A (query tile: 64 rows x 32 chunks, all threads) ----
    #pragma unroll
    for (int i = 0; i < 8; i++) {
        int li  = tid + i * NT;
        int row = li >> 5, cc = li & 31;
        cpasync16(sb + OFF_A + row * 512 + ((cc ^ (row & 7)) << 4),
                  &E4[(size_t)(xbase + qbase + row) * 32 + cc]);
    }
    // ---- async load B tile 0: each group loads its 64-row half ----
    #pragma unroll
    for (int i = 0; i < 16; i++) {
        int c   = lt + i * 128;           // 0..2047: 64 rows x 32 chunks
        int row = c >> 5, cc = c & 31;
        cpasync16(sb + OFF_B + grp * 32768 + row * 512 + ((cc ^ (row & 7)) << 4),
                  &E4[(size_t)(xbase + grp * 64 + row) * 32 + cc]);
    }
    CP_COMMIT();

    // warp tile position and ldmatrix bases
    const int m0 = (wid & 1) * 32;          // 2 m-warps
    const int n0 = (wid >> 1) * 32;         // 4 n-warps (global col offset)
    const int rowA = lane & 15;
    const int lcA  = lane >> 4;
    const int rowB = ((lane & 16) >> 1) + (lane & 7);
    const int lcB  = (lane >> 3) & 1;
    const uint32_t rc = (uint32_t)(lane & 7);

    uint32_t aBase[2];
    #pragma unroll
    for (int mi = 0; mi < 2; mi++)
        aBase[mi] = sb + OFF_A + (m0 + mi * 16 + rowA) * 512;
    uint32_t bBase[2];
    #pragma unroll
    for (int ni2 = 0; ni2 < 2; ni2++)
        bBase[ni2] = sb + OFF_B + grp * 32768
                   + (n0 - grp * 64 + ni2 * 16 + rowB) * 512;

    // per-thread rows (4) and their top-3 lists
    const int rr   = lane >> 2;
    const int colb = (lane & 3) * 2;
    int Rl[4] = {m0 + rr, m0 + rr + 8, m0 + 16 + rr, m0 + 24 + rr};
    float tv[4][3];
    int   ti[4][3];
    #pragma unroll
    for (int r = 0; r < 4; r++) {
        tv[r][0] = tv[r][1] = tv[r][2] = 3.0e38f;
        ti[r][0] = ti[r][1] = ti[r][2] = 0;
    }

    CP_WAIT0();
    __syncthreads();   // A + both B0 halves resident (one full sync at start)

    for (int ct = 0; ct < NTILE; ct++) {
        // candidate sq for my 8 cols
        float2 q[4];
        #pragma unroll
        for (int ni = 0; ni < 4; ni++)
            q[ni] = __ldg(reinterpret_cast<const float2*>(
                        g_sq + xbase + ct * CT + n0 + ni * 8 + colb));

        // ---- interleaved 3-term MMA, phase-split issue ----
        float d[2][4][4];
        #pragma unroll
        for (int mi = 0; mi < 2; mi++)
            #pragma unroll
            for (int ni = 0; ni < 4; ni++)
                #pragma unroll
                for (int e = 0; e < 4; e++) d[mi][ni][e] = 0.f;

        #pragma unroll
        for (int k = 0; k < 8; k++) {
            // (ch+16)^rc == (ch^rc)+16 since rc<8 -> lo-fragment addr = +256B
            const uint32_t offA = (((uint32_t)(2 * k + lcA) ^ rc) << 4);
            const uint32_t offB = (((uint32_t)(2 * k + lcB) ^ rc) << 4);
            uint32_t ah[2][4], al[2][4], bh[2][4], bl[2][4];

            // hi fragments first: the hh burst below depends only on these
            #pragma unroll
            for (int mi = 0; mi < 2; mi++)
                ldsm4(ah[mi][0], ah[mi][1], ah[mi][2], ah[mi][3],
                      aBase[mi] + offA);
            #pragma unroll
            for (int ni2 = 0; ni2 < 2; ni2++)
                ldsm4(bh[ni2][0], bh[ni2][1], bh[ni2][2], bh[ni2][3],
                      bBase[ni2] + offB);
            // lo fragments issued now; their latency is covered by hh MMAs
            #pragma unroll
            for (int mi = 0; mi < 2; mi++)
                ldsm4(al[mi][0], al[mi][1], al[mi][2], al[mi][3],
                      aBase[mi] + offA + 256);
            #pragma unroll
            for (int ni2 = 0; ni2 < 2; ni2++)
                ldsm4(bl[ni2][0], bl[ni2][1], bl[ni2][2], bl[ni2][3],
                      bBase[ni2] + offB + 256);

            // phase 1: hh (needs only ah/bh)
            #pragma unroll
            for (int mi = 0; mi < 2; mi++)
                #pragma unroll
                for (int ni = 0; ni < 4; ni++)
                    mma16816(d[mi][ni][0], d[mi][ni][1], d[mi][ni][2], d[mi][ni][3],
                             ah[mi][0], ah[mi][1], ah[mi][2], ah[mi][3],
                             bh[ni >> 1][(ni & 1) * 2], bh[ni >> 1][(ni & 1) * 2 + 1]);
            // phase 2: hl
            #pragma unroll
            for (int mi = 0; mi < 2; mi++)
                #pragma unroll
                for (int ni = 0; ni < 4; ni++)
                    mma16816(d[mi][ni][0], d[mi][ni][1], d[mi][ni][2], d[mi][ni][3],
                             ah[mi][0], ah[mi][1], ah[mi][2], ah[mi][3],
                             bl[ni >> 1][(ni & 1) * 2], bl[ni >> 1][(ni & 1) * 2 + 1]);
            // phase 3: lh
            #pragma unroll
            for (int mi = 0; mi < 2; mi++)
                #pragma unroll
                for (int ni = 0; ni < 4; ni++)
                    mma16816(d[mi][ni][0], d[mi][ni][1], d[mi][ni][2], d[mi][ni][3],
                             al[mi][0], al[mi][1], al[mi][2], al[mi][3],
                             bh[ni >> 1][(ni & 1) * 2], bh[ni >> 1][(ni & 1) * 2 + 1]);
        }

        GROUP_BAR(barid);   // my group done reading its half-buffer

        // issue next half-tile for MY group (overlaps epilogue)
        if (ct < NTILE - 1) {
            const int nmb = (ct + 1) * CT + grp * 64;
            #pragma unroll
            for (int i = 0; i < 16; i++) {
                int c   = lt + i * 128;
                int row = c >> 5, cc = c & 31;
                cpasync16(sb + OFF_B + grp * 32768 + row * 512
                          + ((cc ^ (row & 7)) << 4),
                          &E4[(size_t)(xbase + nmb + row) * 32 + cc]);
            }
            CP_COMMIT();
        }

        // ---- in-register top-3 inserts (32 scores per thread) ----
        if (ct == diagTile) {
            #pragma unroll
            for (int mi = 0; mi < 2; mi++)
                #pragma unroll
                for (int eh = 0; eh < 2; eh++) {
                    const int ri  = mi * 2 + eh;
                    const int ngl = qbase + Rl[ri];
                    #pragma unroll
                    for (int ni = 0; ni < 4; ni++) {
                        int   m  = ct * CT + n0 + ni * 8 + colb;
                        float s0 = fmaf(-2.f, d[mi][ni][eh * 2],     q[ni].x);
                        float s1 = fmaf(-2.f, d[mi][ni][eh * 2 + 1], q[ni].y);
                        if (m != ngl)     ins3(s0, m,     tv[ri], ti[ri]);
                        if (m + 1 != ngl) ins3(s1, m + 1, tv[ri], ti[ri]);
                    }
                }
        } else {
            const int mb0 = ct * CT + n0 + colb;
            #pragma unroll
            for (int mi = 0; mi < 2; mi++)
                #pragma unroll
                for (int eh = 0; eh < 2; eh++) {
                    const int ri = mi * 2 + eh;
                    #pragma unroll
                    for (int ni = 0; ni < 4; ni++) {
                        int   m  = mb0 + ni * 8;
                        float s0 = fmaf(-2.f, d[mi][ni][eh * 2],     q[ni].x);
                        float s1 = fmaf(-2.f, d[mi][ni][eh * 2 + 1], q[ni].y);
                        ins3(s0, m,     tv[ri], ti[ri]);
                        ins3(s1, m + 1, tv[ri], ti[ri]);
                    }
                }
        }

        CP_WAIT0();
        GROUP_BAR(barid);   // my group's next half-tile resident
    }

    // ---- merge across the 4 lanes sharing each row: SNAPSHOT then insert ----
    #pragma unroll
    for (int off = 1; off <= 2; off <<= 1) {
        #pragma unroll
        for (int r = 0; r < 4; r++) {
            float sv[3]; int si[3];
            #pragma unroll
            for (int e = 0; e < 3; e++) {
                sv[e] = __shfl_xor_sync(0xffffffffu, tv[r][e], off);
                si[e] = __shfl_xor_sync(0xffffffffu, ti[r][e], off);
            }
            #pragma unroll
            for (int e = 0; e < 3; e++)
                ins3(sv[e], si[e], tv[r], ti[r]);
        }
    }
    // publish per-warp top-3 (4 n-warps per row)
    if ((lane & 3) == 0) {
        const int nw = wid >> 1;
        #pragma unroll
        for (int r = 0; r < 4; r++) {
            int base = (Rl[r] * 4 + nw) * 3;
            #pragma unroll
            for (int e = 0; e < 3; e++) {
                mrgV[base + e] = tv[r][e];
                mrgI[base + e] = ti[r][e];
            }
        }
    }
    __syncthreads();

    // final merge: one thread per row
    if (tid < QT) {
        float ft[3] = {3.0e38f, 3.0e38f, 3.0e38f};
        int   fi[3] = {0, 0, 0};
        #pragma unroll
        for (int nw = 0; nw < 4; nw++) {
            int base = (tid * 4 + nw) * 3;
            #pragma unroll
            for (int e = 0; e < 3; e++)
                ins3(mrgV[base + e], mrgI[base + e], ft, fi);
        }
        sIdx[tid * 3 + 0] = fi[0];
        sIdx[tid * 3 + 1] = fi[1];
        sIdx[tid * 3 + 2] = fi[2];
    }
    __syncthreads();

    // ---- gather + blend: (1-s)*x + (s/3)*(xa+xb+xc), original fp32 data ----
    float s  = fminf(fmaxf(strength[0], 0.f), 1.f);
    float w1 = 1.f - s;
    float w2 = s * (1.f / 3.f);
    const float4* X4 = reinterpret_cast<const float4*>(X + (size_t)b * N_ * D_);
    float* Yb = Y + (size_t)b * N_ * D_;
    for (int r = wid; r < QT; r += NT / 32) {
        int n  = qbase + r;
        int ia = sIdx[r * 3 + 0];
        int ib = sIdx[r * 3 + 1];
        int ic = sIdx[r * 3 + 2];
        float4 vn = X4[(size_t)n  * 32 + lane];
        float4 va = X4[(size_t)ia * 32 + lane];
        float4 vb = X4[(size_t)ib * 32 + lane];
        float4 vc = X4[(size_t)ic * 32 + lane];
        float4 o;
        o.x = w1 * vn.x + w2 * (va.x + vb.x + vc.x);
        o.y = w1 * vn.y + w2 * (va.y + vb.y + vc.y);
        o.z = w1 * vn.z + w2 * (va.z + vb.z + vc.z);
        o.w = w1 * vn.w + w2 * (va.w + vb.w + vc.w);
        reinterpret_cast<float4*>(Yb + (size_t)n * D_)[lane] = o;
    }
}

// ---------------------------------------------------------------------------
extern "C" void kernel_launch(void* const* d_in, const int* in_sizes, int n_in,
                              void* d_out, int out_size) {
    const float* X;
    const float* st;
    if (n_in >= 2 && in_sizes[0] == 1) { st = (const float*)d_in[0]; X = (const float*)d_in[1]; }
    else                               { X = (const float*)d_in[0]; st = (const float*)d_in[1]; }
    float* Y = (float*)d_out;

    int rows = B_ * N_;
    prep_kernel<<<(rows * 32 + 255) / 256, 256>>>(X);

    cudaFuncSetAttribute(knn_mma_kernel,
                         cudaFuncAttributeMaxDynamicSharedMemorySize, SMEM_TOTAL);
    dim3 grid(N_ / QT, B_);
    knn_mma_kernel<<<grid, NT, SMEM_TOTAL>>>(X, st, Y);
}

// round 16
// speedup vs baseline: 1.1520x; 1.0737x over previous
#include <cuda_runtime.h>
#include <cuda_fp16.h>
#include <cstdint>

// Problem constants (ParacrineCascade: B=32, N=2048, D=128, K=3)
#define B_     32
#define N_     2048
#define D_     128
#define QT     64                 // queries per CTA  (2 CTAs/SM)
#define CT     128                // candidates per tile
#define NTILE  (N_ / CT)          // 16
#define NT     256                // threads (8 warps: 2m x 4n, warp tile 32x32)

// smem byte offsets
#define OFF_A    0                // 32KB  query tile (64 rows x 512B)
#define OFF_B    32768            // 64KB: two 32KB group-private half-buffers
#define OFF_MRGV 98304            // 64*4*3 f32 = 3072
#define OFF_MRGI 101376           // 64*4*3 int = 3072
#define OFF_SIDX 104448           // 64*3 int = 768
#define OFF_MBAR 105216           // 2 x 8B mbarriers (one per group)
#define SMEM_TOTAL 105472         // ~103KB -> 2 CTAs/SM

// device scratch (no cudaMalloc allowed)
// g_ext layout: [row][64] u64, PRE-SWIZZLED: 16B chunk cc of the logical row
// lives at slot cc^(row&7) (hi chunks 0..15, lo chunks 16..31; XOR with <8
// stays within each half). A linear copy into smem reproduces exactly the
// swizzled smem image previous rounds built with per-chunk XOR stores.
__device__ float              g_sq [B_ * N_];
__device__ unsigned long long g_ext[(size_t)B_ * N_ * 64];

typedef unsigned long long u64;

__device__ __forceinline__ uint32_t smem_u32(const void* p) {
    uint32_t a;
    asm("{ .reg .u64 t; cvta.to.shared.u64 t, %1; cvt.u32.u64 %0, t; }"
        : "=r"(a) : "l"(p));
    return a;
}
__device__ __forceinline__ void cpasync16(uint32_t dst, const void* src) {
    asm volatile("cp.async.cg.shared.global [%0], [%1], 16;" :: "r"(dst), "l"(src));
}
#define CP_COMMIT() asm volatile("cp.async.commit_group;" ::: "memory")
#define CP_WAIT0()  asm volatile("cp.async.wait_group 0;" ::: "memory")
#define GROUP_BAR(id) asm volatile("bar.sync %0, 128;" :: "r"(id) : "memory")
#define MBAR_INIT(mb, c) asm volatile("mbarrier.init.shared.b64 [%0], %1;" :: "r"(mb), "r"(c) : "memory")

__device__ __forceinline__ void mbar_wait(uint32_t mb, uint32_t parity) {
    uint32_t done;
    asm volatile("{\n\t.reg .pred p;\n\t"
        "mbarrier.try_wait.parity.acquire.cta.shared::cta.b64 p, [%1], %2;\n\t"
        "selp.b32 %0, 1, 0, p;\n\t}"
        : "=r"(done) : "r"(mb), "r"(parity) : "memory");
    if (!done) {
        asm volatile("{\n\t.reg .pred P1;\n\t"
            "WL_%=:\n\t"
            "mbarrier.try_wait.parity.acquire.cta.shared::cta.b64 P1, [%0], %1, 0x989680;\n\t"
            "@P1 bra.uni WD_%=;\n\t"
            "bra.uni WL_%=;\n\t"
            "WD_%=:\n\t}"
            :: "r"(mb), "r"(parity) : "memory");
    }
}

__device__ __forceinline__ void ldsm4(uint32_t& r0, uint32_t& r1,
                                      uint32_t& r2, uint32_t& r3, uint32_t addr) {
    asm volatile("ldmatrix.sync.aligned.m8n8.x4.shared.b16 {%0,%1,%2,%3}, [%4];"
                 : "=r"(r0), "=r"(r1), "=r"(r2), "=r"(r3) : "r"(addr));
}
__device__ __forceinline__ void mma16816(float& d0, float& d1, float& d2, float& d3,
                                         uint32_t a0, uint32_t a1, uint32_t a2, uint32_t a3,
                                         uint32_t b0, uint32_t b1) {
    asm volatile("mma.sync.aligned.m16n8k16.row.col.f32.f16.f16.f32 "
                 "{%0,%1,%2,%3}, {%4,%5,%6,%7}, {%8,%9}, {%0,%1,%2,%3};"
                 : "+f"(d0), "+f"(d1), "+f"(d2), "+f"(d3)
                 : "r"(a0), "r"(a1), "r"(a2), "r"(a3), "r"(b0), "r"(b1));
}

__device__ __forceinline__ void ins3(float s, int m, float* t, int* ix) {
    if (s < t[2]) {
        if (s < t[1]) {
            t[2] = t[1]; ix[2] = ix[1];
            if (s < t[0]) { t[1] = t[0]; ix[1] = ix[0]; t[0] = s; ix[0] = m; }
            else          { t[1] = s; ix[1] = m; }
        } else { t[2] = s; ix[2] = m; }
    }
}

// ---------------------------------------------------------------------------
// prep: squared norms (fp32) + fp16 hi/lo split -> g_ext (pre-swizzled).
// one warp per point. lane owns one float4 = one u64 per array; its 16B chunk
// index is lane>>1, half lane&1 -> swizzled u64 slot 2*((lane>>1)^(row&7)) + (lane&1).
// ---------------------------------------------------------------------------
__global__ void prep_kernel(const float* __restrict__ X) {
    int row  = (blockIdx.x * blockDim.x + threadIdx.x) >> 5;
    int lane = threadIdx.x & 31;
    if (row >= B_ * N_) return;
    float4 v = reinterpret_cast<const float4*>(X)[(size_t)row * 32 + lane];
    float s = v.x * v.x + v.y * v.y + v.z * v.z + v.w * v.w;
    #pragma unroll
    for (int off = 16; off; off >>= 1) s += __shfl_xor_sync(0xffffffffu, s, off);
    if (lane == 0) g_sq[row] = s;

    __half h0 = __float2half_rn(v.x), h1 = __float2half_rn(v.y);
    __half h2 = __float2half_rn(v.z), h3 = __float2half_rn(v.w);
    __half l0 = __float2half_rn(v.x - __half2float(h0));
    __half l1 = __float2half_rn(v.y - __half2float(h1));
    __half l2 = __float2half_rn(v.z - __half2float(h2));
    __half l3 = __float2half_rn(v.w - __half2float(h3));
    u64 hp = (u64)__half_as_ushort(h0)        | ((u64)__half_as_ushort(h1) << 16)
           | ((u64)__half_as_ushort(h2) << 32) | ((u64)__half_as_ushort(h3) << 48);
    u64 lp = (u64)__half_as_ushort(l0)        | ((u64)__half_as_ushort(l1) << 16)
           | ((u64)__half_as_ushort(l2) << 32) | ((u64)__half_as_ushort(l3) << 48);
    int slot = (((lane >> 1) ^ (row & 7)) << 1) + (lane & 1);
    g_ext[(size_t)row * 64 + slot]      = hp;   // hi half (chunks 0..15)
    g_ext[(size_t)row * 64 + 32 + slot] = lp;   // lo half (chunks 16..31)
}

// ---------------------------------------------------------------------------
// main: mma.sync fp16 3-term GEMM, two independent 4-warp groups per CTA.
// R16: pre-swizzled g_ext -> steady-state B tiles arrive via ONE 32KB
// cp.async.bulk per group (mbarrier complete_tx), eliminating 16 LDGSTS
// per thread per tile + their address ALU. Smem image bitwise identical
// to R15 -> identical scores and output.
// grid (32, 32), 256 threads, warp grid 2(m) x 4(n), warp tile 32x32.
// ---------------------------------------------------------------------------
__global__ __launch_bounds__(NT, 2)
void knn_mma_kernel(const float* __restrict__ X,
                    const float* __restrict__ strength,
                    float* __restrict__ Y) {
    extern __shared__ char smem[];
    const uint32_t sb = smem_u32(smem);
    const int tid  = threadIdx.x;
    const int wid  = tid >> 5;
    const int lane = tid & 31;
    const int b     = blockIdx.y;
    const int qbase = blockIdx.x * QT;
    const int xbase = b * N_;
    const int diagTile = blockIdx.x >> 1;   // the only tile containing m==n

    const int grp  = tid >> 7;            // 0: warps 0-3 (n0<64), 1: warps 4-7
    const int lt   = tid & 127;           // thread id within group
    const int barid = 1 + grp;
    const uint32_t mbar = sb + OFF_MBAR + grp * 8;

    const uint4* E4 = reinterpret_cast<const uint4*>(g_ext);  // [row][32] 16B chunks
    float* mrgV = (float*)(smem + OFF_MRGV);
    int*   mrgI = (int*)(smem + OFF_MRGI);
    int*   sIdx = (int*)(smem + OFF_SIDX);

    if (tid < 2) MBAR_INIT(sb + OFF_MBAR + tid * 8, 1);

    // ---- prologue loads: g_ext is pre-swizzled -> pure linear copies ----
    #pragma unroll
    for (int i = 0; i < 8; i++) {
        int li = tid + i * NT;            // 0..2047
        cpasync16(sb + OFF_A + li * 16,
                  &E4[(size_t)(xbase + qbase) * 32 + li]);
    }
    #pragma unroll
    for (int i = 0; i < 16; i++) {
        int c = lt + i * 128;             // 0..2047 within my 32KB half
        cpasync16(sb + OFF_B + grp * 32768 + c * 16,
                  &E4[(size_t)(xbase + grp * 64) * 32 + c]);
    }
    CP_COMMIT();

    // warp tile position and ldmatrix bases
    const int m0 = (wid & 1) * 32;          // 2 m-warps
    const int n0 = (wid >> 1) * 32;         // 4 n-warps (global col offset)
    const int rowA = lane & 15;
    const int lcA  = lane >> 4;
    const int rowB = ((lane & 16) >> 1) + (lane & 7);
    const int lcB  = (lane >> 3) & 1;
    const uint32_t rc = (uint32_t)(lane & 7);

    uint32_t aBase[2];
    #pragma unroll
    for (int mi = 0; mi < 2; mi++)
        aBase[mi] = sb + OFF_A + (m0 + mi * 16 + rowA) * 512;
    uint32_t bBase[2];
    #pragma unroll
    for (int ni2 = 0; ni2 < 2; ni2++)
        bBase[ni2] = sb + OFF_B + grp * 32768
                   + (n0 - grp * 64 + ni2 * 16 + rowB) * 512;

    // per-thread rows (4) and their top-3 lists
    const int rr   = lane >> 2;
    const int colb = (lane & 3) * 2;
    int Rl[4] = {m0 + rr, m0 + rr + 8, m0 + 16 + rr, m0 + 24 + rr};
    float tv[4][3];
    int   ti[4][3];
    #pragma unroll
    for (int r = 0; r < 4; r++) {
        tv[r][0] = tv[r][1] = tv[r][2] = 3.0e38f;
        ti[r][0] = ti[r][1] = ti[r][2] = 0;
    }

    CP_WAIT0();
    __syncthreads();   // A + both B0 halves resident; mbarriers initialized

    for (int ct = 0; ct < NTILE; ct++) {
        // candidate sq for my 8 cols
        float2 q[4];
        #pragma unroll
        for (int ni = 0; ni < 4; ni++)
            q[ni] = __ldg(reinterpret_cast<const float2*>(
                        g_sq + xbase + ct * CT + n0 + ni * 8 + colb));

        // ---- interleaved 3-term MMA, phase-split issue ----
        float d[2][4][4];
        #pragma unroll
        for (int mi = 0; mi < 2; mi++)
            #pragma unroll
            for (int ni = 0; ni < 4; ni++)
                #pragma unroll
                for (int e = 0; e < 4; e++) d[mi][ni][e] = 0.f;

        #pragma unroll
        for (int k = 0; k < 8; k++) {
            const uint32_t offA = (((uint32_t)(2 * k + lcA) ^ rc) << 4);
            const uint32_t offB = (((uint32_t)(2 * k + lcB) ^ rc) << 4);
            uint32_t ah[2][4], al[2][4], bh[2][4], bl[2][4];

            #pragma unroll
            for (int mi = 0; mi < 2; mi++)
                ldsm4(ah[mi][0], ah[mi][1], ah[mi][2], ah[mi][3],
                      aBase[mi] + offA);
            #pragma unroll
            for (int ni2 = 0; ni2 < 2; ni2++)
                ldsm4(bh[ni2][0], bh[ni2][1], bh[ni2][2], bh[ni2][3],
                      bBase[ni2] + offB);
            #pragma unroll
            for (int mi = 0; mi < 2; mi++)
                ldsm4(al[mi][0], al[mi][1], al[mi][2], al[mi][3],
                      aBase[mi] + offA + 256);
            #pragma unroll
            for (int ni2 = 0; ni2 < 2; ni2++)
                ldsm4(bl[ni2][0], bl[ni2][1], bl[ni2][2], bl[ni2][3],
                      bBase[ni2] + offB + 256);

            #pragma unroll
            for (int mi = 0; mi < 2; mi++)
                #pragma unroll
                for (int ni = 0; ni < 4; ni++)
                    mma16816(d[mi][ni][0], d[mi][ni][1], d[mi][ni][2], d[mi][ni][3],
                             ah[mi][0], ah[mi][1], ah[mi][2], ah[mi][3],
                             bh[ni >> 1][(ni & 1) * 2], bh[ni >> 1][(ni & 1) * 2 + 1]);
            #pragma unroll
            for (int mi = 0; mi < 2; mi++)
                #pragma unroll
                for (int ni = 0; ni < 4; ni++)
                    mma16816(d[mi][ni][0], d[mi][ni][1], d[mi][ni][2], d[mi][ni][3],
                             ah[mi][0], ah[mi][1], ah[mi][2], ah[mi][3],
                             bl[ni >> 1][(ni & 1) * 2], bl[ni >> 1][(ni & 1) * 2 + 1]);
            #pragma unroll
            for (int mi = 0; mi < 2; mi++)
                #pragma unroll
                for (int ni = 0; ni < 4; ni++)
                    mma16816(d[mi][ni][0], d[mi][ni][1], d[mi][ni][2], d[mi][ni][3],
                             al[mi][0], al[mi][1], al[mi][2], al[mi][3],
                             bh[ni >> 1][(ni & 1) * 2], bh[ni >> 1][(ni & 1) * 2 + 1]);
        }

        GROUP_BAR(barid);   // my group done reading its half-buffer

        // one bulk copy brings the next half-tile (overlaps epilogue)
        if (ct < NTILE - 1 && lt == 0) {
            const char* src = (const char*)g_ext
                            + (size_t)(xbase + (ct + 1) * CT + grp * 64) * 512;
            asm volatile("mbarrier.arrive.expect_tx.shared.b64 _, [%0], %1;"
                         :: "r"(mbar), "r"(32768u) : "memory");
            asm volatile("cp.async.bulk.shared::cluster.global.mbarrier::complete_tx::bytes "
                         "[%0], [%1], %2, [%3];"
                         :: "r"(sb + OFF_B + grp * 32768), "l"(src),
                            "r"(32768u), "r"(mbar) : "memory");
        }

        // ---- in-register top-3 inserts (32 scores per thread) ----
        if (ct == diagTile) {
            #pragma unroll
            for (int mi = 0; mi < 2; mi++)
                #pragma unroll
                for (int eh = 0; eh < 2; eh++) {
                    const int ri  = mi * 2 + eh;
                    const int ngl = qbase + Rl[ri];
                    #pragma unroll
                    for (int ni = 0; ni < 4; ni++) {
                        int   m  = ct * CT + n0 + ni * 8 + colb;
                        float s0 = fmaf(-2.f, d[mi][ni][eh * 2],     q[ni].x);
                        float s1 = fmaf(-2.f, d[mi][ni][eh * 2 + 1], q[ni].y);
                        if (m != ngl)     ins3(s0, m,     tv[ri], ti[ri]);
                        if (m + 1 != ngl) ins3(s1, m + 1, tv[ri], ti[ri]);
                    }
                }
        } else {
            const int mb0 = ct * CT + n0 + colb;
            #pragma unroll
            for (int mi = 0; mi < 2; mi++)
                #pragma unroll
                for (int eh = 0; eh < 2; eh++) {
                    const int ri = mi * 2 + eh;
                    #pragma unroll
                    for (int ni = 0; ni < 4; ni++) {
                        int   m  = mb0 + ni * 8;
                        float s0 = fmaf(-2.f, d[mi][ni][eh * 2],     q[ni].x);
                        float s1 = fmaf(-2.f, d[mi][ni][eh * 2 + 1], q[ni].y);
                        ins3(s0, m,     tv[ri], ti[ri]);
                        ins3(s1, m + 1, tv[ri], ti[ri]);
                    }
                }
        }

        if (ct < NTILE - 1) mbar_wait(mbar, (uint32_t)(ct & 1));
        GROUP_BAR(barid);   // my group's next half-tile resident
    }

    // ---- merge across the 4 lanes sharing each row: SNAPSHOT then insert ----
    #pragma unroll
    for (int off = 1; off <= 2; off <<= 1) {
        #pragma unroll
        for (int r = 0; r < 4; r++) {
            float sv[3]; int si[3];
            #pragma unroll
            for (int e = 0; e < 3; e++) {
                sv[e] = __shfl_xor_sync(0xffffffffu, tv[r][e], off);
                si[e] = __shfl_xor_sync(0xffffffffu, ti[r][e], off);
            }
            #pragma unroll
            for (int e = 0; e < 3; e++)
                ins3(sv[e], si[e], tv[r], ti[r]);
        }
    }
    // publish per-warp top-3 (4 n-warps per row)
    if ((lane & 3) == 0) {
        const int nw = wid >> 1;
        #pragma unroll
        for (int r = 0; r < 4; r++) {
            int base = (Rl[r] * 4 + nw) * 3;
            #pragma unroll
            for (int e = 0; e < 3; e++) {
                mrgV[base + e] = tv[r][e];
                mrgI[base + e] = ti[r][e];
            }
        }
    }
    __syncthreads();

    // final merge: one thread per row
    if (tid < QT) {
        float ft[3] = {3.0e38f, 3.0e38f, 3.0e38f};
        int   fi[3] = {0, 0, 0};
        #pragma unroll
        for (int nw = 0; nw < 4; nw++) {
            int base = (tid * 4 + nw) * 3;
            #pragma unroll
            for (int e = 0; e < 3; e++)
                ins3(mrgV[base + e], mrgI[base + e], ft, fi);
        }
        sIdx[tid * 3 + 0] = fi[0];
        sIdx[tid * 3 + 1] = fi[1];
        sIdx[tid * 3 + 2] = fi[2];
    }
    __syncthreads();

    // ---- gather + blend: (1-s)*x + (s/3)*(xa+xb+xc), original fp32 data ----
    float s  = fminf(fmaxf(strength[0], 0.f), 1.f);
    float w1 = 1.f - s;
    float w2 = s * (1.f / 3.f);
    const float4* X4 = reinterpret_cast<const float4*>(X + (size_t)b * N_ * D_);
    float* Yb = Y + (size_t)b * N_ * D_;
    for (int r = wid; r < QT; r += NT / 32) {
        int n  = qbase + r;
        int ia = sIdx[r * 3 + 0];
        int ib = sIdx[r * 3 + 1];
        int ic = sIdx[r * 3 + 2];
        float4 vn = X4[(size_t)n  * 32 + lane];
        float4 va = X4[(size_t)ia * 32 + lane];
        float4 vb = X4[(size_t)ib * 32 + lane];
        float4 vc = X4[(size_t)ic * 32 + lane];
        float4 o;
        o.x = w1 * vn.x + w2 * (va.x + vb.x + vc.x);
        o.y = w1 * vn.y + w2 * (va.y + vb.y + vc.y);
        o.z = w1 * vn.z + w2 * (va.z + vb.z + vc.z);
        o.w = w1 * vn.w + w2 * (va.w + vb.w + vc.w);
        reinterpret_cast<float4*>(Yb + (size_t)n * D_)[lane] = o;
    }
}

// ---------------------------------------------------------------------------
extern "C" void kernel_launch(void* const* d_in, const int* in_sizes, int n_in,
                              void* d_out, int out_size) {
    const float* X;
    const float* st;
    if (n_in >= 2 && in_sizes[0] == 1) { st = (const float*)d_in[0]; X = (const float*)d_in[1]; }
    else                               { X = (const float*)d_in[0]; st = (const float*)d_in[1]; }
    float* Y = (float*)d_out;

    int rows = B_ * N_;
    prep_kernel<<<(rows * 32 + 255) / 256, 256>>>(X);

    cudaFuncSetAttribute(knn_mma_kernel,
                         cudaFuncAttributeMaxDynamicSharedMemorySize, SMEM_TOTAL);
    dim3 grid(N_ / QT, B_);
    knn_mma_kernel<<<grid, NT, SMEM_TOTAL>>>(X, st, Y);
}